// round 6
// baseline (speedup 1.0000x reference)
#include <cuda_runtime.h>
#include <math.h>

#define D 32
#define H 128
#define NB 128
#define NSTEPS 8
#define DTf 0.125f
#define LOG2PI 1.837877066409345483560659472811f

// C = W1 @ W3 (HxH), c = W1 @ b3, E[m,k] = W2[m,k] * C[k,m]
__device__ float g_C[H * H];
__device__ float g_E[H * H];
__device__ float g_cv[H];

static __device__ constexpr float Aa[6][5] = {
    {0.f, 0.f, 0.f, 0.f, 0.f},
    {0.2f, 0.f, 0.f, 0.f, 0.f},
    {3.f/40.f, 9.f/40.f, 0.f, 0.f, 0.f},
    {44.f/45.f, -56.f/15.f, 32.f/9.f, 0.f, 0.f},
    {19372.f/6561.f, -25360.f/2187.f, 64448.f/6561.f, -212.f/729.f, 0.f},
    {9017.f/3168.f, -355.f/33.f, 46732.f/5247.f, 49.f/176.f, -5103.f/18656.f}
};
static __device__ constexpr float Bb[6] = {
    35.f/384.f, 0.f, 500.f/1113.f, 125.f/192.f, -2187.f/6784.f, 11.f/84.f
};
static __device__ constexpr float Cc[6] = {0.f, 0.2f, 0.3f, 0.8f, 8.f/9.f, 1.f};

__global__ void precompute_C_kernel(const float* __restrict__ W1,
                                    const float* __restrict__ W3,
                                    const float* __restrict__ b3) {
    __shared__ float w1row[D];
    __shared__ float b3s[D];
    int r = blockIdx.x, k = threadIdx.x;
    if (k < D) { w1row[k] = W1[r * D + k]; b3s[k] = b3[k]; }
    __syncthreads();
    float acc = 0.f;
#pragma unroll
    for (int j = 0; j < D; j++) acc += w1row[j] * W3[j * H + k];
    g_C[r * H + k] = acc;
    if (k == 0) {
        float s = 0.f;
#pragma unroll
        for (int j = 0; j < D; j++) s += w1row[j] * b3s[j];
        g_cv[r] = s;
    }
}

__global__ void precompute_E_kernel(const float* __restrict__ W2) {
    int m = blockIdx.x, k = threadIdx.x;
    g_E[m * H + k] = W2[m * H + k] * g_C[k * H + m];
}

__device__ __forceinline__ float ftanh(float z) {
    float e = __expf(2.f * z);
    return 1.f - __fdividef(2.f, e + 1.f);
}

// dynamic smem layout (floats)
#define OFF_H1   0
#define OFF_D1   128
#define OFF_H2S  256                 // 48*128
#define OFF_PE   (256 + 6144)        // 48*128
#define OFF_P1   (256 + 12288)       // 48*32
#define OFF_P2   (256 + 12288 + 1536)
#define OFF_X    (256 + 12288 + 3072)
#define OFF_FIN  (OFF_X + 32)
#define OFF_KV   (OFF_FIN + 16)      // 6*32
#define SMEM_FLOATS (OFF_KV + 192)
#define SMEM_BYTES  (SMEM_FLOATS * 4)

__global__ __launch_bounds__(256, 1)
void ode_kernel(const float* __restrict__ x0,
                const float* __restrict__ W1g,
                const float* __restrict__ u1g,
                const float* __restrict__ b1g,
                const float* __restrict__ W2g,
                const float* __restrict__ b2g,
                const float* __restrict__ W3g,
                const float* __restrict__ b3g,
                const float* __restrict__ precg,
                float* __restrict__ out)
{
    extern __shared__ float sm[];
    float* sh1  = sm + OFF_H1;
    float* sd1  = sm + OFF_D1;
    float* sh2s = sm + OFF_H2S;
    float* spE  = sm + OFF_PE;
    float* sp1  = sm + OFF_P1;
    float* sp2  = sm + OFF_P2;
    float* sx   = sm + OFF_X;
    float* sfin = sm + OFF_FIN;
    float* skv  = sm + OFF_KV;

    const int tid  = threadIdx.x;
    const int lane = tid & 31;
    const int wid  = tid >> 5;
    const int r2   = tid >> 1;   // hidden row (pair)
    const int half = tid & 1;
    const int r3   = tid >> 3;   // output row (8 threads/row)
    const int sub  = tid & 7;
    const int b    = blockIdx.x;

    // ---- register-resident weights ----
    float4 Cv[16], W2v[16], Ev[16], W3c[4];
    {
        const float4* c4 = (const float4*)(g_C + r2 * H + half * 64);
        const float4* q  = (const float4*)(W2g + r2 * H + half * 64);
        const float4* e  = (const float4*)(g_E + r2 * H + half * 64);
#pragma unroll
        for (int i = 0; i < 16; i++) { Cv[i] = c4[i]; W2v[i] = q[i]; Ev[i] = e[i]; }
        const float4* w3 = (const float4*)(W3g + r3 * H + sub * 16);
#pragma unroll
        for (int i = 0; i < 4; i++) W3c[i] = w3[i];
    }
    const float u1r = u1g[r2];
    const float b1r = b1g[r2];
    const float b2r = b2g[r2];
    const float b3r = b3g[r3];
    const float prr = precg[r3];
    const float cr  = g_cv[r2];

    // prologue: x0 -> smem, P0 = W1 x0 per row (pair-split)
    if (tid < D) sx[tid] = x0[b * D + tid];
    float xreg = x0[b * D + r3];   // owners (sub==0) use these
    float yreg = xreg;
    __syncthreads();

    float Py;
    {
        const float4* w1p = (const float4*)(W1g + r2 * D + half * 16);
        const float4* xv  = ((const float4*)sx) + half * 4;
        float a0 = 0.f, a1 = 0.f, a2 = 0.f, a3 = 0.f;
#pragma unroll
        for (int i = 0; i < 4; i++) {
            float4 w = w1p[i], x4 = xv[i];
            a0 = fmaf(w.x, x4.x, a0); a1 = fmaf(w.y, x4.y, a1);
            a2 = fmaf(w.z, x4.z, a2); a3 = fmaf(w.w, x4.w, a3);
        }
        float p = (a0 + a1) + (a2 + a3);
        p += __shfl_xor_sync(0xffffffffu, p, 1);
        Py = p;
    }
    float P = Py;
    float v[6];

#pragma unroll 1
    for (int step = 0; step < NSTEPS; step++) {
        const float t0 = (float)step * DTf;
#pragma unroll
        for (int s = 0; s < 6; s++) {
            const float t = t0 + Cc[s] * DTf;
            const int si = step * 6 + s;

            // ---- phase 1 (registers only): h1 = tanh(P + t u1 + b1) ----
            {
                float h = ftanh(P + t * u1r + b1r);
                if (!half) {
                    sh1[r2] = h;
                    sd1[r2] = fmaf(-h, h, 1.f);
                }
            }
            __syncthreads();

            // ---- phase 2: h2 = tanh(W2 h1 + b2); aux pE = E d1 (deferred trace) ----
            {
                const float4* hv = ((const float4*)sh1) + half * 16;
                const float4* dv = ((const float4*)sd1) + half * 16;
                float a0 = 0.f, a1 = 0.f, a2 = 0.f, a3 = 0.f;
                float g0 = 0.f, g1 = 0.f, g2 = 0.f, g3 = 0.f;
#pragma unroll
                for (int c = 0; c < 16; c++) {
                    float4 h4 = hv[c], w = W2v[c];
                    a0 = fmaf(w.x, h4.x, a0); a1 = fmaf(w.y, h4.y, a1);
                    a2 = fmaf(w.z, h4.z, a2); a3 = fmaf(w.w, h4.w, a3);
                    float4 d4 = dv[c], e = Ev[c];
                    g0 = fmaf(e.x, d4.x, g0); g1 = fmaf(e.y, d4.y, g1);
                    g2 = fmaf(e.z, d4.z, g2); g3 = fmaf(e.w, d4.w, g3);
                }
                float pz = (a0 + a1) + (a2 + a3);
                pz += __shfl_xor_sync(0xffffffffu, pz, 1);
                float gs = (g0 + g1) + (g2 + g3);
                gs += __shfl_xor_sync(0xffffffffu, gs, 1);
                float h2 = ftanh(pz + b2r);
                if (!half) {
                    sh2s[si * 128 + r2] = h2;
                    spE[si * 128 + r2]  = gs;
                }
            }
            __syncthreads();

            // ---- phase 3: v_s = C h2 + c; P update; aux k = W3 h2 + x-track ----
            {
                const float* h2cur = sh2s + si * 128;
                const float4* hv = ((const float4*)h2cur) + half * 16;
                float a0 = 0.f, a1 = 0.f, a2 = 0.f, a3 = 0.f;
#pragma unroll
                for (int c = 0; c < 16; c++) {
                    float4 h4 = hv[c], w = Cv[c];
                    a0 = fmaf(w.x, h4.x, a0); a1 = fmaf(w.y, h4.y, a1);
                    a2 = fmaf(w.z, h4.z, a2); a3 = fmaf(w.w, h4.w, a3);
                }
                float vs = (a0 + a1) + (a2 + a3);
                vs += __shfl_xor_sync(0xffffffffu, vs, 1);
                vs += cr;
                v[s] = vs;
                if (s < 5) {
                    float acc = Aa[s + 1][s] * vs;
#pragma unroll
                    for (int l = 0; l < s; l++)
                        acc += Aa[s + 1][l] * v[l];
                    P = Py + DTf * acc;
                } else {
                    Py += DTf * (Bb[0] * v[0] + Bb[2] * v[2] + Bb[3] * v[3]
                               + Bb[4] * v[4] + Bb[5] * v[5]);
                    P = Py;
                }

                // aux: k_s row = W3 h2 (8 threads/row)
                const float4* h3 = ((const float4*)h2cur) + sub * 4;
                float c0 = 0.f, c1 = 0.f, c2 = 0.f, c3 = 0.f;
#pragma unroll
                for (int c = 0; c < 4; c++) {
                    float4 w = W3c[c], h4 = h3[c];
                    c0 = fmaf(w.x, h4.x, c0); c1 = fmaf(w.y, h4.y, c1);
                    c2 = fmaf(w.z, h4.z, c2); c3 = fmaf(w.w, h4.w, c3);
                }
                float o = (c0 + c1) + (c2 + c3);
                o += __shfl_xor_sync(0xffffffffu, o, 1);
                o += __shfl_xor_sync(0xffffffffu, o, 2);
                o += __shfl_xor_sync(0xffffffffu, o, 4);
                if (sub == 0) {
                    o += b3r;
                    skv[s * 32 + r3] = o;
                    float xs = xreg;
                    int idx = si * 32 + r3;
                    sp1[idx] = (-0.5f * xs * xs - 0.5f * LOG2PI) * o;
                    sp2[idx] = (-prr * xs) * o;
                    float xn;
                    if (s < 5) {
                        float acc = Aa[s + 1][s] * o;
#pragma unroll
                        for (int l = 0; l < s; l++)
                            acc += Aa[s + 1][l] * skv[l * 32 + r3];
                        xn = yreg + DTf * acc;
                    } else {
                        float acc = Bb[0] * skv[0 * 32 + r3] + Bb[2] * skv[2 * 32 + r3]
                                  + Bb[3] * skv[3 * 32 + r3] + Bb[4] * skv[4 * 32 + r3]
                                  + Bb[5] * o;
                        xn = yreg + DTf * acc;
                        yreg = xn;
                    }
                    xreg = xn;
                }
            }
            // no barrier: next phase 1 is register-only; sh1/sd1 writes are
            // ordered against phase-2 readers by the phase-1 barrier.
        }
    }
    __syncthreads();   // sp1/sp2/skv/owner state visible for epilogue

    // ---- z output straight from owner registers ----
    if (sub == 0) out[b * D + r3] = yreg;

    // ---- epilogue: warp w (0..7) reduces step w's 6 stages ----
    {
        float ldw = 0.f, klw = 0.f;
        const int stp = wid;
#pragma unroll
        for (int s = 0; s < 6; s++) {
            if (s == 1) continue;  // Bb[1] == 0
            int si = stp * 6 + s;
            float v1 = sp1[si * 32 + lane];
            float v2 = sp2[si * 32 + lane];
            float v3 = 0.f;
#pragma unroll
            for (int rr = 0; rr < 4; rr++) {
                int r = lane + rr * 32;
                float h2v = sh2s[si * 128 + r];
                v3 += fmaf(-h2v, h2v, 1.f) * spE[si * 128 + r];
            }
#pragma unroll
            for (int o = 16; o; o >>= 1) {
                v1 += __shfl_xor_sync(0xffffffffu, v1, o);
                v2 += __shfl_xor_sync(0xffffffffu, v2, o);
                v3 += __shfl_xor_sync(0xffffffffu, v3, o);
            }
            float t = (float)stp * DTf + Cc[s] * DTf;
            float omt = 1.f - t;
            float dlp = -v3;
            float dkl = -0.5f * omt * omt * v1
                        - 0.5f * omt * (1.f + t) * v2
                        + omt * dlp;
            ldw += Bb[s] * dlp;
            klw += Bb[s] * dkl;
        }
        if (lane == 0) { sfin[stp] = ldw; sfin[8 + stp] = klw; }
    }
    __syncthreads();

    if (wid == 0) {
        float a = (lane < 8) ? sfin[lane] : 0.f;
        float k = (lane < 8) ? sfin[8 + lane] : 0.f;
        float xv = x0[b * D + lane];
        float lp = -0.5f * xv * xv - 0.5f * LOG2PI;
#pragma unroll
        for (int o = 16; o; o >>= 1) {
            a  += __shfl_xor_sync(0xffffffffu, a, o);
            k  += __shfl_xor_sync(0xffffffffu, k, o);
            lp += __shfl_xor_sync(0xffffffffu, lp, o);
        }
        if (lane == 0) {
            out[NB * D + b]      = lp + DTf * a;
            out[NB * D + NB + b] = DTf * k;
        }
    }
}

extern "C" void kernel_launch(void* const* d_in, const int* in_sizes, int n_in,
                              void* d_out, int out_size) {
    const float* x0   = (const float*)d_in[0];
    const float* W1   = (const float*)d_in[1];
    const float* u1   = (const float*)d_in[2];
    const float* b1   = (const float*)d_in[3];
    const float* W2   = (const float*)d_in[4];
    const float* b2   = (const float*)d_in[5];
    const float* W3   = (const float*)d_in[6];
    const float* b3   = (const float*)d_in[7];
    const float* prec = (const float*)d_in[8];
    float* out = (float*)d_out;

    cudaFuncSetAttribute(ode_kernel, cudaFuncAttributeMaxDynamicSharedMemorySize, SMEM_BYTES);

    precompute_C_kernel<<<H, H>>>(W1, W3, b3);
    precompute_E_kernel<<<H, H>>>(W2);
    ode_kernel<<<NB, 256, SMEM_BYTES>>>(x0, W1, u1, b1, W2, b2, W3, b3, prec, out);
}